// round 1
// baseline (speedup 1.0000x reference)
#include <cuda_runtime.h>
#include <cstddef>

// Problem constants
constexpr int Bn = 2, Tn = 2048, Cn = 1024, Hn = 16, Dn = 64;
constexpr int Mn = Bn * Tn;          // 4096 rows
constexpr int NQKV = 3 * Cn;         // 3072

// Scratch (device globals -- no allocation allowed)
__device__ __align__(16) float g_q[(size_t)Bn * Hn * Tn * Dn];
__device__ __align__(16) float g_k[(size_t)Bn * Hn * Tn * Dn];
__device__ __align__(16) float g_v[(size_t)Bn * Hn * Tn * Dn];
__device__ __align__(16) float g_y[(size_t)Mn * Cn];

// ---------------------------------------------------------------------------
// Tiled fp32 GEMM: C = A[M,K] @ B[K,N] + bias
// BM=BN=128, BK=16, 256 threads, 8x8 per thread.
// EPI==0: QKV epilogue -> scatter into g_q/g_k/g_v with [B,H,T,D] layout
// EPI==1: plain epilogue -> out[m*Cn + n]; A is read from g_y
// ---------------------------------------------------------------------------
template <int EPI>
__global__ __launch_bounds__(256, 2)
void gemm_kernel(const float* __restrict__ A, const float* __restrict__ Bw,
                 const float* __restrict__ bias, float* __restrict__ out,
                 int K, int ldb)
{
    constexpr int BM = 128, BN = 128, BK = 16;
    __shared__ float As[BK][BM];   // A tile stored transposed
    __shared__ float Bs[BK][BN];

    const int tid = threadIdx.x;
    const int tx = tid & 15, ty = tid >> 4;
    const int m0 = blockIdx.y * BM;
    const int n0 = blockIdx.x * BN;

    const float* Aptr = (EPI == 0) ? A : g_y;
    const int lda = K;

    float acc[8][8] = {};

    for (int k0 = 0; k0 < K; k0 += BK) {
        // Load A tile (128x16), store transposed
        #pragma unroll
        for (int it = 0; it < 2; it++) {
            int idx = tid + it * 256;
            int r   = idx >> 2;            // 0..127
            int c4  = (idx & 3) << 2;      // 0,4,8,12
            float4 v = *(const float4*)&Aptr[(size_t)(m0 + r) * lda + k0 + c4];
            As[c4 + 0][r] = v.x;
            As[c4 + 1][r] = v.y;
            As[c4 + 2][r] = v.z;
            As[c4 + 3][r] = v.w;
        }
        // Load B tile (16x128)
        #pragma unroll
        for (int it = 0; it < 2; it++) {
            int idx = tid + it * 256;
            int r   = idx >> 5;            // 0..15
            int c4  = (idx & 31) << 2;     // 0..124
            *(float4*)&Bs[r][c4] =
                *(const float4*)&Bw[(size_t)(k0 + r) * ldb + n0 + c4];
        }
        __syncthreads();

        #pragma unroll
        for (int kk = 0; kk < BK; kk++) {
            float a[8], b[8];
            *(float4*)&a[0] = *(float4*)&As[kk][ty * 8];
            *(float4*)&a[4] = *(float4*)&As[kk][ty * 8 + 4];
            *(float4*)&b[0] = *(float4*)&Bs[kk][tx * 8];
            *(float4*)&b[4] = *(float4*)&Bs[kk][tx * 8 + 4];
            #pragma unroll
            for (int i = 0; i < 8; i++)
                #pragma unroll
                for (int j = 0; j < 8; j++)
                    acc[i][j] += a[i] * b[j];
        }
        __syncthreads();
    }

    // Epilogue
    #pragma unroll
    for (int i = 0; i < 8; i++) {
        int gm = m0 + ty * 8 + i;
        #pragma unroll
        for (int j = 0; j < 8; j++) {
            int gn = n0 + tx * 8 + j;
            float val = acc[i][j] + bias[gn];
            if (EPI == 0) {
                int which = gn >> 10;          // 0=q,1=k,2=v
                int cc    = gn & 1023;
                int h     = cc >> 6;
                int d     = cc & 63;
                int b     = gm >> 11;          // /2048
                int t     = gm & 2047;
                size_t off = ((size_t)((b << 4) + h) * Tn + t) * Dn + d;
                float* dst = (which == 0) ? g_q : (which == 1) ? g_k : g_v;
                dst[off] = val;
            } else {
                out[(size_t)gm * Cn + gn] = val;
            }
        }
    }
}

// ---------------------------------------------------------------------------
// Flash attention (fp32, online softmax, causal)
// One block per (b*h, q-tile of 64). 256 threads: 16x16 grid, 4x4 micro-tile.
// Shared: Q, K, V, P tiles (64 x 68 pad) + reduction scratch.
// ---------------------------------------------------------------------------
constexpr int PAD = 68;
constexpr int ATTN_SMEM_FLOATS = 4 * 64 * PAD + 64 * 16 + 128;
constexpr int ATTN_SMEM_BYTES  = ATTN_SMEM_FLOATS * 4;

__global__ __launch_bounds__(256, 2)
void attn_kernel()
{
    extern __shared__ float sm[];
    float* Qs  = sm;
    float* Ks  = Qs + 64 * PAD;
    float* Vs  = Ks + 64 * PAD;
    float* Ps  = Vs + 64 * PAD;
    float* red = Ps + 64 * PAD;    // [64][16]
    float* m_s = red + 64 * 16;    // [64]
    float* l_s = m_s + 64;         // [64]

    const int tid = threadIdx.x;
    const int tx = tid & 15, ty = tid >> 4;
    const int qt = blockIdx.x;         // q tile (0..31)
    const int bh = blockIdx.y;         // b*16 + h (0..31)
    const size_t base = (size_t)bh * Tn * Dn;
    const int q0 = qt * 64;

    // Load Q tile [64][64]
    #pragma unroll
    for (int it = 0; it < 4; it++) {
        int idx = tid + it * 256;
        int r   = idx >> 4;
        int c4  = (idx & 15) << 2;
        *(float4*)&Qs[r * PAD + c4] =
            *(const float4*)&g_q[base + (size_t)(q0 + r) * Dn + c4];
    }
    if (tid < 64) { m_s[tid] = -1e30f; l_s[tid] = 0.0f; }

    float acc[4][4] = {};

    for (int kt = 0; kt <= qt; kt++) {
        __syncthreads();   // protect Ks/Vs/Ps/red from previous iteration readers
        const int k0 = kt * 64;
        #pragma unroll
        for (int it = 0; it < 4; it++) {
            int idx = tid + it * 256;
            int r   = idx >> 4;
            int c4  = (idx & 15) << 2;
            *(float4*)&Ks[r * PAD + c4] =
                *(const float4*)&g_k[base + (size_t)(k0 + r) * Dn + c4];
            *(float4*)&Vs[r * PAD + c4] =
                *(const float4*)&g_v[base + (size_t)(k0 + r) * Dn + c4];
        }
        __syncthreads();

        // S = Q @ K^T  (4x4 micro-tile per thread)
        float s[4][4] = {};
        #pragma unroll 4
        for (int d = 0; d < 64; d += 4) {
            float qv[4][4], kv[4][4];
            #pragma unroll
            for (int i = 0; i < 4; i++) {
                float4 v = *(float4*)&Qs[(ty * 4 + i) * PAD + d];
                qv[i][0] = v.x; qv[i][1] = v.y; qv[i][2] = v.z; qv[i][3] = v.w;
            }
            #pragma unroll
            for (int j = 0; j < 4; j++) {
                float4 v = *(float4*)&Ks[(tx * 4 + j) * PAD + d];
                kv[j][0] = v.x; kv[j][1] = v.y; kv[j][2] = v.z; kv[j][3] = v.w;
            }
            #pragma unroll
            for (int i = 0; i < 4; i++)
                #pragma unroll
                for (int j = 0; j < 4; j++)
                    #pragma unroll
                    for (int dd = 0; dd < 4; dd++)
                        s[i][j] += qv[i][dd] * kv[j][dd];
        }

        // scale + causal mask + per-thread row max
        const bool diag = (kt == qt);
        float pmax[4];
        #pragma unroll
        for (int i = 0; i < 4; i++) {
            pmax[i] = -1e30f;
            #pragma unroll
            for (int j = 0; j < 4; j++) {
                float v = s[i][j] * 0.125f;  // 1/sqrt(64)
                if (diag && (tx * 4 + j) > (ty * 4 + i)) v = -1e30f;
                s[i][j] = v;
                pmax[i] = fmaxf(pmax[i], v);
            }
        }
        #pragma unroll
        for (int i = 0; i < 4; i++) red[(ty * 4 + i) * 16 + tx] = pmax[i];
        __syncthreads();

        float mnew[4], alpha[4], psum[4];
        #pragma unroll
        for (int i = 0; i < 4; i++) {
            const int r = ty * 4 + i;
            float mo = m_s[r];
            float m  = mo;
            #pragma unroll
            for (int t2 = 0; t2 < 16; t2++) m = fmaxf(m, red[r * 16 + t2]);
            mnew[i]  = m;
            alpha[i] = __expf(mo - m);
            float ps = 0.0f;
            #pragma unroll
            for (int j = 0; j < 4; j++) {
                float p = __expf(s[i][j] - m);
                Ps[r * PAD + tx * 4 + j] = p;
                ps += p;
            }
            psum[i] = ps;
        }
        __syncthreads();   // all reads of red(max)/m_s done
        #pragma unroll
        for (int i = 0; i < 4; i++) red[(ty * 4 + i) * 16 + tx] = psum[i];
        __syncthreads();   // red(sum) + Ps ready
        if (tx == 0) {
            #pragma unroll
            for (int i = 0; i < 4; i++) {
                const int r = ty * 4 + i;
                float ssum = 0.0f;
                #pragma unroll
                for (int t2 = 0; t2 < 16; t2++) ssum += red[r * 16 + t2];
                l_s[r] = l_s[r] * alpha[i] + ssum;
                m_s[r] = mnew[i];
            }
        }

        // O = O*alpha + P @ V
        #pragma unroll
        for (int i = 0; i < 4; i++)
            #pragma unroll
            for (int j = 0; j < 4; j++)
                acc[i][j] *= alpha[i];

        #pragma unroll 4
        for (int k = 0; k < 64; k += 4) {
            float pv[4][4], vv[4][4];
            #pragma unroll
            for (int i = 0; i < 4; i++) {
                float4 v = *(float4*)&Ps[(ty * 4 + i) * PAD + k];
                pv[i][0] = v.x; pv[i][1] = v.y; pv[i][2] = v.z; pv[i][3] = v.w;
            }
            #pragma unroll
            for (int kk = 0; kk < 4; kk++) {
                float4 v = *(float4*)&Vs[(k + kk) * PAD + tx * 4];
                vv[kk][0] = v.x; vv[kk][1] = v.y; vv[kk][2] = v.z; vv[kk][3] = v.w;
            }
            #pragma unroll
            for (int i = 0; i < 4; i++)
                #pragma unroll
                for (int j = 0; j < 4; j++)
                    #pragma unroll
                    for (int kk = 0; kk < 4; kk++)
                        acc[i][j] += pv[i][kk] * vv[kk][j];
        }
    }

    __syncthreads();   // l_s final values visible
    const int b = bh >> 4, h = bh & 15;
    #pragma unroll
    for (int i = 0; i < 4; i++) {
        const int r = ty * 4 + i;
        const float inv = 1.0f / l_s[r];
        const int t = q0 + r;
        #pragma unroll
        for (int j = 0; j < 4; j++) {
            g_y[(size_t)(b * Tn + t) * Cn + h * Dn + tx * 4 + j] = acc[i][j] * inv;
        }
    }
}

// ---------------------------------------------------------------------------
extern "C" void kernel_launch(void* const* d_in, const int* in_sizes, int n_in,
                              void* d_out, int out_size)
{
    const float* x      = (const float*)d_in[0];
    const float* w_attn = (const float*)d_in[1];
    const float* b_attn = (const float*)d_in[2];
    const float* w_proj = (const float*)d_in[3];
    const float* b_proj = (const float*)d_in[4];
    float* out = (float*)d_out;

    cudaFuncSetAttribute(attn_kernel,
                         cudaFuncAttributeMaxDynamicSharedMemorySize,
                         ATTN_SMEM_BYTES);

    // 1) QKV = x @ w_attn + b_attn, scattered to [B,H,T,D]
    gemm_kernel<0><<<dim3(NQKV / 128, Mn / 128), 256>>>(
        x, w_attn, b_attn, nullptr, Cn, NQKV);

    // 2) Flash attention per (b*h, q-tile)
    attn_kernel<<<dim3(Tn / 64, Bn * Hn), 256, ATTN_SMEM_BYTES>>>();

    // 3) out = y @ w_proj + b_proj
    gemm_kernel<1><<<dim3(Cn / 128, Mn / 128), 256>>>(
        nullptr, w_proj, b_proj, out, Cn, Cn);
}

// round 3
// speedup vs baseline: 3.6468x; 3.6468x over previous
#include <cuda_runtime.h>
#include <cstdint>
#include <cstddef>

// Problem constants
constexpr int Bn = 2, Tn = 2048, Cn = 1024, Hn = 16, Dn = 64;
constexpr int Mn = Bn * Tn;          // 4096
constexpr int NQKV = 3 * Cn;         // 3072

// Scratch (device globals -- no allocation allowed)
__device__ __align__(16) float g_q[(size_t)Mn * Cn];
__device__ __align__(16) float g_k[(size_t)Mn * Cn];
__device__ __align__(16) float g_v[(size_t)Mn * Cn];
__device__ __align__(16) float g_y[(size_t)Mn * Cn];

__device__ __forceinline__ uint32_t f2t(float f) {
    uint32_t u;
    asm("cvt.rna.tf32.f32 %0, %1;" : "=r"(u) : "f"(f));
    return u;
}

// D += A(16x8 tf32) @ B(8x8 tf32), fp32 accum
__device__ __forceinline__ void mma8(float* c, const uint32_t* a, const uint32_t* b) {
    asm volatile(
        "mma.sync.aligned.m16n8k8.row.col.f32.tf32.tf32.f32 "
        "{%0,%1,%2,%3},{%4,%5,%6,%7},{%8,%9},{%0,%1,%2,%3};\n"
        : "+f"(c[0]), "+f"(c[1]), "+f"(c[2]), "+f"(c[3])
        : "r"(a[0]), "r"(a[1]), "r"(a[2]), "r"(a[3]), "r"(b[0]), "r"(b[1]));
}

// ---------------------------------------------------------------------------
// TF32 tensor-core GEMM: C = A[M,K] @ B[K,N] + bias
// 256 threads = 8 warps as (2 M) x (4 N); warp tile 64x32; BK=16.
// EPI==0: QKV epilogue -> scatter into g_q/g_k/g_v ([B,H,T,D])
// EPI==1: plain epilogue -> out[m*Cn + n]; A read from g_y
// ---------------------------------------------------------------------------
template <int EPI>
__global__ __launch_bounds__(256, 2)
void gemm_tc(const float* __restrict__ A, const float* __restrict__ Bw,
             const float* __restrict__ bias, float* __restrict__ out,
             int K, int ldb)
{
    constexpr int BM = 128, BN = 128, BK = 16;
    constexpr int APITCH = 20;    // As[m][k] pitch -> conflict-free frag reads
    constexpr int BPITCH = 136;   // Bs[k][n] pitch -> conflict-free frag reads
    __shared__ uint32_t As[BM * APITCH];
    __shared__ uint32_t Bs[BK * BPITCH];

    const int tid  = threadIdx.x;
    const int lane = tid & 31;
    const int w    = tid >> 5;
    const int wm   = w & 1;       // warp M (0..1)
    const int wn   = w >> 1;      // warp N (0..3)
    const int g    = lane >> 2;   // group id (row within frag)
    const int c    = lane & 3;    // thread-in-group (col within frag)

    const int m0 = blockIdx.y * BM;
    const int n0 = blockIdx.x * BN;

    const float* Aptr = (EPI == 0) ? A : g_y;

    float acc[4][4][4] = {};      // [mtile][ntile][frag]

    for (int k0 = 0; k0 < K; k0 += BK) {
        // Load A tile 128x16 (row-major, convert to tf32)
        #pragma unroll
        for (int it = 0; it < 2; it++) {
            int idx = tid + it * 256;
            int r   = idx >> 2;
            int c4  = (idx & 3) << 2;
            float4 v = *(const float4*)&Aptr[(size_t)(m0 + r) * K + k0 + c4];
            uint32_t* p = &As[r * APITCH + c4];
            p[0] = f2t(v.x); p[1] = f2t(v.y); p[2] = f2t(v.z); p[3] = f2t(v.w);
        }
        // Load B tile 16x128
        #pragma unroll
        for (int it = 0; it < 2; it++) {
            int idx = tid + it * 256;
            int r   = idx >> 5;
            int c4  = (idx & 31) << 2;
            float4 v = *(const float4*)&Bw[(size_t)(k0 + r) * ldb + n0 + c4];
            uint32_t* p = &Bs[r * BPITCH + c4];
            p[0] = f2t(v.x); p[1] = f2t(v.y); p[2] = f2t(v.z); p[3] = f2t(v.w);
        }
        __syncthreads();

        #pragma unroll
        for (int ks = 0; ks < BK; ks += 8) {
            uint32_t af[4][4];
            #pragma unroll
            for (int mt = 0; mt < 4; mt++) {
                int mr = wm * 64 + mt * 16 + g;
                int kc = ks + c;
                af[mt][0] = As[mr * APITCH + kc];
                af[mt][1] = As[(mr + 8) * APITCH + kc];
                af[mt][2] = As[mr * APITCH + kc + 4];
                af[mt][3] = As[(mr + 8) * APITCH + kc + 4];
            }
            #pragma unroll
            for (int nt = 0; nt < 4; nt++) {
                uint32_t bf[2];
                int nn = wn * 32 + nt * 8 + g;
                bf[0] = Bs[(ks + c) * BPITCH + nn];
                bf[1] = Bs[(ks + c + 4) * BPITCH + nn];
                #pragma unroll
                for (int mt = 0; mt < 4; mt++)
                    mma8(acc[mt][nt], af[mt], bf);
            }
        }
        __syncthreads();
    }

    // Epilogue
    #pragma unroll
    for (int mt = 0; mt < 4; mt++) {
        #pragma unroll
        for (int nt = 0; nt < 4; nt++) {
            int r0 = m0 + wm * 64 + mt * 16 + g;
            int c0 = n0 + wn * 32 + nt * 8 + 2 * c;
            #pragma unroll
            for (int e = 0; e < 4; e++) {
                int gm = r0 + (e >> 1) * 8;
                int gn = c0 + (e & 1);
                float val = acc[mt][nt][e] + bias[gn];
                if (EPI == 0) {
                    int which = gn >> 10;          // 0=q,1=k,2=v
                    int cc    = gn & 1023;
                    int h     = cc >> 6;
                    int d     = cc & 63;
                    int b     = gm >> 11;
                    int t     = gm & 2047;
                    size_t off = ((size_t)((b << 4) + h) * Tn + t) * Dn + d;
                    float* dst = (which == 0) ? g_q : (which == 1) ? g_k : g_v;
                    dst[off] = val;
                } else {
                    out[(size_t)gm * Cn + gn] = val;
                }
            }
        }
    }
}

// ---------------------------------------------------------------------------
// Flash attention on tensor cores (tf32 mma, fp32 softmax, causal).
// Block = (b*h, q-tile of 64). 128 threads = 4 warps, each warp owns 16 rows.
// Smem: QP (Q tile, later P tile) pitch 68; Ks pitch 68; Vs pitch 72.
// ---------------------------------------------------------------------------
constexpr int QK_PITCH = 68;
constexpr int V_PITCH  = 72;
constexpr int ATTN_SMEM_U32 = 2 * 64 * QK_PITCH + 64 * V_PITCH;
constexpr int ATTN_SMEM_BYTES = ATTN_SMEM_U32 * 4;

__global__ __launch_bounds__(128, 2)
void attn_tc()
{
    extern __shared__ uint32_t smu[];
    uint32_t* QP = smu;                       // Q tile, then P tile
    uint32_t* Ks = smu + 64 * QK_PITCH;
    uint32_t* Vs = smu + 2 * 64 * QK_PITCH;

    const int tid  = threadIdx.x;
    const int lane = tid & 31;
    const int w    = tid >> 5;
    const int g    = lane >> 2;
    const int c    = lane & 3;

    const int qt = (gridDim.x - 1) - blockIdx.x;   // heavy tiles first
    const int bh = blockIdx.y;
    const size_t base = (size_t)bh * Tn * Dn;
    const int q0 = qt * 64;

    // Stage Q tile into smem (tf32)
    #pragma unroll
    for (int it = 0; it < 8; it++) {
        int idx = tid + it * 128;
        int r   = idx >> 4;
        int c4  = (idx & 15) << 2;
        float4 v = *(const float4*)&g_q[base + (size_t)(q0 + r) * Dn + c4];
        uint32_t* p = &QP[r * QK_PITCH + c4];
        p[0] = f2t(v.x); p[1] = f2t(v.y); p[2] = f2t(v.z); p[3] = f2t(v.w);
    }
    __syncthreads();

    // Preload Q fragments (warp's 16 rows x full 64 K-dim -> 8 ksteps)
    const int r0 = w * 16 + g;                // local row this thread owns
    uint32_t qf[8][4];
    #pragma unroll
    for (int ks = 0; ks < 8; ks++) {
        int kc = ks * 8 + c;
        qf[ks][0] = QP[r0 * QK_PITCH + kc];
        qf[ks][1] = QP[(r0 + 8) * QK_PITCH + kc];
        qf[ks][2] = QP[r0 * QK_PITCH + kc + 4];
        qf[ks][3] = QP[(r0 + 8) * QK_PITCH + kc + 4];
    }

    float oacc[8][4] = {};
    float m0r = -1e30f, m1r = -1e30f, l0r = 0.0f, l1r = 0.0f;

    for (int kt = 0; kt <= qt; kt++) {
        __syncthreads();     // prior iteration's readers of Ks/Vs/QP done
        const int k0 = kt * 64;
        #pragma unroll
        for (int it = 0; it < 8; it++) {
            int idx = tid + it * 128;
            int r   = idx >> 4;
            int c4  = (idx & 15) << 2;
            float4 kv = *(const float4*)&g_k[base + (size_t)(k0 + r) * Dn + c4];
            uint32_t* pk = &Ks[r * QK_PITCH + c4];
            pk[0] = f2t(kv.x); pk[1] = f2t(kv.y); pk[2] = f2t(kv.z); pk[3] = f2t(kv.w);
            float4 vv = *(const float4*)&g_v[base + (size_t)(k0 + r) * Dn + c4];
            uint32_t* pv = &Vs[r * V_PITCH + c4];
            pv[0] = f2t(vv.x); pv[1] = f2t(vv.y); pv[2] = f2t(vv.z); pv[3] = f2t(vv.w);
        }
        __syncthreads();

        // S = Q @ K^T  (warp rows x 64 keys)
        float sacc[8][4] = {};
        #pragma unroll
        for (int ks = 0; ks < 8; ks++) {
            #pragma unroll
            for (int nt = 0; nt < 8; nt++) {
                uint32_t bf[2];
                int nn = nt * 8 + g;
                int kc = ks * 8 + c;
                bf[0] = Ks[nn * QK_PITCH + kc];
                bf[1] = Ks[nn * QK_PITCH + kc + 4];
                mma8(sacc[nt], qf[ks], bf);
            }
        }

        // scale + causal mask + per-thread partial row max
        const bool diag = (kt == qt);
        float tmax0 = -1e30f, tmax1 = -1e30f;
        #pragma unroll
        for (int nt = 0; nt < 8; nt++) {
            int cc0 = nt * 8 + 2 * c;
            #pragma unroll
            for (int e = 0; e < 4; e++) {
                float v = sacc[nt][e] * 0.125f;   // 1/sqrt(64)
                int col = cc0 + (e & 1);
                int row = (e < 2) ? r0 : (r0 + 8);
                if (diag && col > row) v = -1e30f;
                sacc[nt][e] = v;
                if (e < 2) tmax0 = fmaxf(tmax0, v);
                else       tmax1 = fmaxf(tmax1, v);
            }
        }
        // quad-wide row reductions (lanes sharing a row differ only in lane&3)
        tmax0 = fmaxf(tmax0, __shfl_xor_sync(0xffffffffu, tmax0, 1));
        tmax0 = fmaxf(tmax0, __shfl_xor_sync(0xffffffffu, tmax0, 2));
        tmax1 = fmaxf(tmax1, __shfl_xor_sync(0xffffffffu, tmax1, 1));
        tmax1 = fmaxf(tmax1, __shfl_xor_sync(0xffffffffu, tmax1, 2));

        float mn0 = fmaxf(m0r, tmax0), mn1 = fmaxf(m1r, tmax1);
        float al0 = __expf(m0r - mn0), al1 = __expf(m1r - mn1);

        float ps0 = 0.0f, ps1 = 0.0f;
        #pragma unroll
        for (int nt = 0; nt < 8; nt++) {
            int cc0 = nt * 8 + 2 * c;
            float p00 = __expf(sacc[nt][0] - mn0);
            float p01 = __expf(sacc[nt][1] - mn0);
            float p10 = __expf(sacc[nt][2] - mn1);
            float p11 = __expf(sacc[nt][3] - mn1);
            ps0 += p00 + p01;
            ps1 += p10 + p11;
            QP[r0 * QK_PITCH + cc0]           = f2t(p00);
            QP[r0 * QK_PITCH + cc0 + 1]       = f2t(p01);
            QP[(r0 + 8) * QK_PITCH + cc0]     = f2t(p10);
            QP[(r0 + 8) * QK_PITCH + cc0 + 1] = f2t(p11);
        }
        ps0 += __shfl_xor_sync(0xffffffffu, ps0, 1);
        ps0 += __shfl_xor_sync(0xffffffffu, ps0, 2);
        ps1 += __shfl_xor_sync(0xffffffffu, ps1, 1);
        ps1 += __shfl_xor_sync(0xffffffffu, ps1, 2);

        l0r = l0r * al0 + ps0;  m0r = mn0;
        l1r = l1r * al1 + ps1;  m1r = mn1;

        // O *= alpha (row-wise)
        #pragma unroll
        for (int nt = 0; nt < 8; nt++) {
            oacc[nt][0] *= al0; oacc[nt][1] *= al0;
            oacc[nt][2] *= al1; oacc[nt][3] *= al1;
        }

        __syncwarp();   // each warp reads only its own P rows

        // O += P @ V
        #pragma unroll
        for (int ks = 0; ks < 8; ks++) {
            uint32_t af[4];
            int kc = ks * 8 + c;
            af[0] = QP[r0 * QK_PITCH + kc];
            af[1] = QP[(r0 + 8) * QK_PITCH + kc];
            af[2] = QP[r0 * QK_PITCH + kc + 4];
            af[3] = QP[(r0 + 8) * QK_PITCH + kc + 4];
            #pragma unroll
            for (int nt = 0; nt < 8; nt++) {
                uint32_t bf[2];
                int nn = nt * 8 + g;
                bf[0] = Vs[(ks * 8 + c) * V_PITCH + nn];
                bf[1] = Vs[(ks * 8 + c + 4) * V_PITCH + nn];
                mma8(oacc[nt], af, bf);
            }
        }
    }

    // Epilogue: O /= l, write to g_y [B,T,C]
    const float inv0 = 1.0f / l0r, inv1 = 1.0f / l1r;
    const int b = bh >> 4, h = bh & 15;
    #pragma unroll
    for (int nt = 0; nt < 8; nt++) {
        int d0 = nt * 8 + 2 * c;
        size_t o0 = ((size_t)(b * Tn + q0 + r0)) * Cn + h * 64 + d0;
        g_y[o0]     = oacc[nt][0] * inv0;
        g_y[o0 + 1] = oacc[nt][1] * inv0;
        size_t o1 = ((size_t)(b * Tn + q0 + r0 + 8)) * Cn + h * 64 + d0;
        g_y[o1]     = oacc[nt][2] * inv1;
        g_y[o1 + 1] = oacc[nt][3] * inv1;
    }
}

// ---------------------------------------------------------------------------
extern "C" void kernel_launch(void* const* d_in, const int* in_sizes, int n_in,
                              void* d_out, int out_size)
{
    const float* x      = (const float*)d_in[0];
    const float* w_attn = (const float*)d_in[1];
    const float* b_attn = (const float*)d_in[2];
    const float* w_proj = (const float*)d_in[3];
    const float* b_proj = (const float*)d_in[4];
    float* out = (float*)d_out;

    cudaFuncSetAttribute(attn_tc,
                         cudaFuncAttributeMaxDynamicSharedMemorySize,
                         ATTN_SMEM_BYTES);

    // 1) QKV = x @ w_attn + b_attn, scattered to [B,H,T,D]
    gemm_tc<0><<<dim3(NQKV / 128, Mn / 128), 256>>>(
        x, w_attn, b_attn, nullptr, Cn, NQKV);

    // 2) Flash attention
    attn_tc<<<dim3(Tn / 64, Bn * Hn), 128, ATTN_SMEM_BYTES>>>();

    // 3) out = y @ w_proj + b_proj
    gemm_tc<1><<<dim3(Cn / 128, Mn / 128), 256>>>(
        nullptr, w_proj, b_proj, out, Cn, Cn);
}

// round 4
// speedup vs baseline: 4.1448x; 1.1366x over previous
#include <cuda_runtime.h>
#include <cstdint>
#include <cstddef>

// Problem constants
constexpr int Bn = 2, Tn = 2048, Cn = 1024, Hn = 16, Dn = 64;
constexpr int Mn = Bn * Tn;          // 4096
constexpr int NQKV = 3 * Cn;         // 3072

// Scratch (device globals -- no allocation allowed)
// g_q/g_k/g_v/g_y and g_xt/g_wa/g_wp hold tf32 bit patterns in float containers.
__device__ __align__(16) float g_q[(size_t)Mn * Cn];
__device__ __align__(16) float g_k[(size_t)Mn * Cn];
__device__ __align__(16) float g_v[(size_t)Mn * Cn];
__device__ __align__(16) float g_y[(size_t)Mn * Cn];
__device__ __align__(16) float g_xt[(size_t)Mn * Cn];
__device__ __align__(16) float g_wa[(size_t)Cn * NQKV];
__device__ __align__(16) float g_wp[(size_t)Cn * Cn];

__device__ __forceinline__ uint32_t f2t(float f) {
    uint32_t u;
    asm("cvt.rna.tf32.f32 %0, %1;" : "=r"(u) : "f"(f));
    return u;
}

__device__ __forceinline__ void cpa16(uint32_t dst, const void* src) {
    asm volatile("cp.async.cg.shared.global [%0], [%1], 16;" :: "r"(dst), "l"(src));
}
__device__ __forceinline__ void cp_commit() {
    asm volatile("cp.async.commit_group;");
}
template <int N>
__device__ __forceinline__ void cp_wait() {
    asm volatile("cp.async.wait_group %0;" :: "n"(N));
}

// D += A(16x8 tf32) @ B(8x8 tf32), fp32 accum
__device__ __forceinline__ void mma8(float* c, const uint32_t* a, const uint32_t* b) {
    asm volatile(
        "mma.sync.aligned.m16n8k8.row.col.f32.tf32.tf32.f32 "
        "{%0,%1,%2,%3},{%4,%5,%6,%7},{%8,%9},{%0,%1,%2,%3};\n"
        : "+f"(c[0]), "+f"(c[1]), "+f"(c[2]), "+f"(c[3])
        : "r"(a[0]), "r"(a[1]), "r"(a[2]), "r"(a[3]), "r"(b[0]), "r"(b[1]));
}

// ---------------------------------------------------------------------------
// Pre-conversion: fp32 -> tf32 bits (elementwise, vectorized)
// DST: 0 = g_xt, 1 = g_wa, 2 = g_wp
// ---------------------------------------------------------------------------
template <int DST>
__global__ void cvt_tf32(const float* __restrict__ in, int n4)
{
    float* outp = (DST == 0) ? g_xt : (DST == 1) ? g_wa : g_wp;
    int i = blockIdx.x * 256 + threadIdx.x;
    if (i < n4) {
        float4 v = ((const float4*)in)[i];
        uint4 o;
        o.x = f2t(v.x); o.y = f2t(v.y); o.z = f2t(v.z); o.w = f2t(v.w);
        ((uint4*)outp)[i] = o;
    }
}

// ---------------------------------------------------------------------------
// TF32 tensor-core GEMM, cp.async double-buffered.
// C = A[M,K] @ B[K,N] + bias. 256 threads = 8 warps (2M x 4N), warp 64x32.
// EPI==0: A=g_xt, B=g_wa, ldb=NQKV; epilogue scatters tf32 into g_q/g_k/g_v.
// EPI==1: A=g_y,  B=g_wp, ldb=Cn;   epilogue writes fp32 out.
// ---------------------------------------------------------------------------
template <int EPI>
__global__ __launch_bounds__(256, 2)
void gemm_tc(const float* __restrict__ bias, float* __restrict__ out)
{
    constexpr int BM = 128, BN = 128, BK = 16;
    constexpr int AP = 20;     // As[m][k] pitch (conflict-free frag reads)
    constexpr int BP = 136;    // Bs[k][n] pitch
    constexpr int K   = Cn;
    constexpr int ldb = (EPI == 0) ? NQKV : Cn;
    __shared__ uint32_t As[2][BM * AP];
    __shared__ uint32_t Bs[2][BK * BP];

    const float* A  = (EPI == 0) ? g_xt : g_y;
    const float* Bw = (EPI == 0) ? g_wa : g_wp;

    const int tid  = threadIdx.x;
    const int lane = tid & 31;
    const int w    = tid >> 5;
    const int wm   = w & 1;
    const int wn   = w >> 1;
    const int g    = lane >> 2;
    const int c    = lane & 3;

    const int m0 = blockIdx.y * BM;
    const int n0 = blockIdx.x * BN;

    auto load_stage = [&](int k0, int s) {
        uint32_t ab = (uint32_t)__cvta_generic_to_shared(&As[s][0]);
        uint32_t bb = (uint32_t)__cvta_generic_to_shared(&Bs[s][0]);
        #pragma unroll
        for (int it = 0; it < 2; it++) {
            int idx = tid + it * 256;
            int r   = idx >> 2;
            int c4  = (idx & 3) << 2;
            cpa16(ab + (r * AP + c4) * 4, &A[(size_t)(m0 + r) * K + k0 + c4]);
        }
        #pragma unroll
        for (int it = 0; it < 2; it++) {
            int idx = tid + it * 256;
            int r   = idx >> 5;
            int c4  = (idx & 31) << 2;
            cpa16(bb + (r * BP + c4) * 4, &Bw[(size_t)(k0 + r) * ldb + n0 + c4]);
        }
        cp_commit();
    };

    float acc[4][4][4] = {};

    constexpr int NIT = K / BK;    // 64
    load_stage(0, 0);

    for (int it = 0; it < NIT; it++) {
        const int s = it & 1;
        if (it + 1 < NIT) {
            load_stage((it + 1) * BK, s ^ 1);
            cp_wait<1>();
        } else {
            cp_wait<0>();
        }
        __syncthreads();

        #pragma unroll
        for (int ks = 0; ks < BK; ks += 8) {
            uint32_t af[4][4];
            #pragma unroll
            for (int mt = 0; mt < 4; mt++) {
                int mr = wm * 64 + mt * 16 + g;
                int kc = ks + c;
                af[mt][0] = As[s][mr * AP + kc];
                af[mt][1] = As[s][(mr + 8) * AP + kc];
                af[mt][2] = As[s][mr * AP + kc + 4];
                af[mt][3] = As[s][(mr + 8) * AP + kc + 4];
            }
            #pragma unroll
            for (int nt = 0; nt < 4; nt++) {
                uint32_t bf[2];
                int nn = wn * 32 + nt * 8 + g;
                bf[0] = Bs[s][(ks + c) * BP + nn];
                bf[1] = Bs[s][(ks + c + 4) * BP + nn];
                #pragma unroll
                for (int mt = 0; mt < 4; mt++)
                    mma8(acc[mt][nt], af[mt], bf);
            }
        }
        __syncthreads();
    }

    // Epilogue
    #pragma unroll
    for (int mt = 0; mt < 4; mt++) {
        #pragma unroll
        for (int nt = 0; nt < 4; nt++) {
            int r0 = m0 + wm * 64 + mt * 16 + g;
            int c0 = n0 + wn * 32 + nt * 8 + 2 * c;
            #pragma unroll
            for (int e = 0; e < 4; e++) {
                int gm = r0 + (e >> 1) * 8;
                int gn = c0 + (e & 1);
                float val = acc[mt][nt][e] + bias[gn];
                if (EPI == 0) {
                    int which = gn >> 10;          // 0=q,1=k,2=v
                    int cc    = gn & 1023;
                    int h     = cc >> 6;
                    int d     = cc & 63;
                    int b     = gm >> 11;
                    int t     = gm & 2047;
                    size_t off = ((size_t)((b << 4) + h) * Tn + t) * Dn + d;
                    float* dst = (which == 0) ? g_q : (which == 1) ? g_k : g_v;
                    dst[off] = __uint_as_float(f2t(val));   // store tf32 bits
                } else {
                    out[(size_t)gm * Cn + gn] = val;
                }
            }
        }
    }
}

// ---------------------------------------------------------------------------
// Flash attention, tf32 mma, fp32 softmax, causal; cp.async double-buffered
// K/V tiles. Block = (b*h, q-tile of 64), 128 threads = 4 warps x 16 rows.
// ---------------------------------------------------------------------------
constexpr int QK_PITCH = 68;
constexpr int V_PITCH  = 72;
constexpr int ATTN_SMEM_U32 = 64 * QK_PITCH + 2 * 64 * QK_PITCH + 2 * 64 * V_PITCH;
constexpr int ATTN_SMEM_BYTES = ATTN_SMEM_U32 * 4;   // 89088

__global__ __launch_bounds__(128, 2)
void attn_tc()
{
    extern __shared__ uint32_t smu[];
    uint32_t* QP  = smu;                                   // Q tile, then P tile
    uint32_t* KsB = smu + 64 * QK_PITCH;                   // 2 K buffers
    uint32_t* VsB = smu + 64 * QK_PITCH + 2 * 64 * QK_PITCH;  // 2 V buffers

    const int tid  = threadIdx.x;
    const int lane = tid & 31;
    const int w    = tid >> 5;
    const int g    = lane >> 2;
    const int c    = lane & 3;

    const int qt = (gridDim.x - 1) - blockIdx.x;   // heavy tiles first
    const int bh = blockIdx.y;
    const size_t base = (size_t)bh * Tn * Dn;
    const int q0 = qt * 64;

    auto prefetch = [&](int kt, int s) {
        uint32_t kb = (uint32_t)__cvta_generic_to_shared(KsB + s * 64 * QK_PITCH);
        uint32_t vb = (uint32_t)__cvta_generic_to_shared(VsB + s * 64 * V_PITCH);
        const float* kp = &g_k[base + (size_t)kt * 64 * Dn];
        const float* vp = &g_v[base + (size_t)kt * 64 * Dn];
        #pragma unroll
        for (int itr = 0; itr < 8; itr++) {
            int idx = tid + itr * 128;
            int r   = idx >> 4;
            int c4  = (idx & 15) << 2;
            cpa16(kb + (r * QK_PITCH + c4) * 4, kp + r * Dn + c4);
            cpa16(vb + (r * V_PITCH  + c4) * 4, vp + r * Dn + c4);
        }
        cp_commit();
    };

    prefetch(0, 0);   // overlap first K/V fetch with Q staging

    // Stage Q tile (already tf32 bits)
    #pragma unroll
    for (int it = 0; it < 8; it++) {
        int idx = tid + it * 128;
        int r   = idx >> 4;
        int c4  = (idx & 15) << 2;
        float4 v = *(const float4*)&g_q[base + (size_t)(q0 + r) * Dn + c4];
        uint32_t* p = &QP[r * QK_PITCH + c4];
        p[0] = __float_as_uint(v.x); p[1] = __float_as_uint(v.y);
        p[2] = __float_as_uint(v.z); p[3] = __float_as_uint(v.w);
    }
    __syncthreads();

    // Preload Q fragments (warp's 16 rows x 64 K-dim -> 8 ksteps)
    const int r0 = w * 16 + g;
    uint32_t qf[8][4];
    #pragma unroll
    for (int ks = 0; ks < 8; ks++) {
        int kc = ks * 8 + c;
        qf[ks][0] = QP[r0 * QK_PITCH + kc];
        qf[ks][1] = QP[(r0 + 8) * QK_PITCH + kc];
        qf[ks][2] = QP[r0 * QK_PITCH + kc + 4];
        qf[ks][3] = QP[(r0 + 8) * QK_PITCH + kc + 4];
    }

    float oacc[8][4] = {};
    float m0r = -1e30f, m1r = -1e30f, l0r = 0.0f, l1r = 0.0f;

    for (int kt = 0; kt <= qt; kt++) {
        const int s = kt & 1;
        if (kt < qt) {
            prefetch(kt + 1, s ^ 1);
            cp_wait<1>();
        } else {
            cp_wait<0>();
        }
        __syncthreads();

        const uint32_t* Ks = KsB + s * 64 * QK_PITCH;
        const uint32_t* Vs = VsB + s * 64 * V_PITCH;

        // S = Q @ K^T
        float sacc[8][4] = {};
        #pragma unroll
        for (int ks = 0; ks < 8; ks++) {
            #pragma unroll
            for (int nt = 0; nt < 8; nt++) {
                uint32_t bf[2];
                int nn = nt * 8 + g;
                int kc = ks * 8 + c;
                bf[0] = Ks[nn * QK_PITCH + kc];
                bf[1] = Ks[nn * QK_PITCH + kc + 4];
                mma8(sacc[nt], qf[ks], bf);
            }
        }

        // scale + causal mask + row max
        const bool diag = (kt == qt);
        float tmax0 = -1e30f, tmax1 = -1e30f;
        #pragma unroll
        for (int nt = 0; nt < 8; nt++) {
            int cc0 = nt * 8 + 2 * c;
            #pragma unroll
            for (int e = 0; e < 4; e++) {
                float v = sacc[nt][e] * 0.125f;
                int col = cc0 + (e & 1);
                int row = (e < 2) ? r0 : (r0 + 8);
                if (diag && col > row) v = -1e30f;
                sacc[nt][e] = v;
                if (e < 2) tmax0 = fmaxf(tmax0, v);
                else       tmax1 = fmaxf(tmax1, v);
            }
        }
        tmax0 = fmaxf(tmax0, __shfl_xor_sync(0xffffffffu, tmax0, 1));
        tmax0 = fmaxf(tmax0, __shfl_xor_sync(0xffffffffu, tmax0, 2));
        tmax1 = fmaxf(tmax1, __shfl_xor_sync(0xffffffffu, tmax1, 1));
        tmax1 = fmaxf(tmax1, __shfl_xor_sync(0xffffffffu, tmax1, 2));

        float mn0 = fmaxf(m0r, tmax0), mn1 = fmaxf(m1r, tmax1);
        float al0 = __expf(m0r - mn0), al1 = __expf(m1r - mn1);

        float ps0 = 0.0f, ps1 = 0.0f;
        #pragma unroll
        for (int nt = 0; nt < 8; nt++) {
            int cc0 = nt * 8 + 2 * c;
            float p00 = __expf(sacc[nt][0] - mn0);
            float p01 = __expf(sacc[nt][1] - mn0);
            float p10 = __expf(sacc[nt][2] - mn1);
            float p11 = __expf(sacc[nt][3] - mn1);
            ps0 += p00 + p01;
            ps1 += p10 + p11;
            QP[r0 * QK_PITCH + cc0]           = f2t(p00);
            QP[r0 * QK_PITCH + cc0 + 1]       = f2t(p01);
            QP[(r0 + 8) * QK_PITCH + cc0]     = f2t(p10);
            QP[(r0 + 8) * QK_PITCH + cc0 + 1] = f2t(p11);
        }
        ps0 += __shfl_xor_sync(0xffffffffu, ps0, 1);
        ps0 += __shfl_xor_sync(0xffffffffu, ps0, 2);
        ps1 += __shfl_xor_sync(0xffffffffu, ps1, 1);
        ps1 += __shfl_xor_sync(0xffffffffu, ps1, 2);

        l0r = l0r * al0 + ps0;  m0r = mn0;
        l1r = l1r * al1 + ps1;  m1r = mn1;

        #pragma unroll
        for (int nt = 0; nt < 8; nt++) {
            oacc[nt][0] *= al0; oacc[nt][1] *= al0;
            oacc[nt][2] *= al1; oacc[nt][3] *= al1;
        }

        __syncwarp();   // each warp reads only its own P rows

        // O += P @ V
        #pragma unroll
        for (int ks = 0; ks < 8; ks++) {
            uint32_t af[4];
            int kc = ks * 8 + c;
            af[0] = QP[r0 * QK_PITCH + kc];
            af[1] = QP[(r0 + 8) * QK_PITCH + kc];
            af[2] = QP[r0 * QK_PITCH + kc + 4];
            af[3] = QP[(r0 + 8) * QK_PITCH + kc + 4];
            #pragma unroll
            for (int nt = 0; nt < 8; nt++) {
                uint32_t bf[2];
                int nn = nt * 8 + g;
                bf[0] = Vs[(ks * 8 + c) * V_PITCH + nn];
                bf[1] = Vs[(ks * 8 + c + 4) * V_PITCH + nn];
                mma8(oacc[nt], af, bf);
            }
        }
        __syncthreads();   // buffer s free for prefetch in iteration kt+1
    }

    // Epilogue: O /= l, write tf32 bits to g_y [B,T,C]
    const float inv0 = 1.0f / l0r, inv1 = 1.0f / l1r;
    const int b = bh >> 4, h = bh & 15;
    #pragma unroll
    for (int nt = 0; nt < 8; nt++) {
        int d0 = nt * 8 + 2 * c;
        size_t o0 = ((size_t)(b * Tn + q0 + r0)) * Cn + h * 64 + d0;
        g_y[o0]     = __uint_as_float(f2t(oacc[nt][0] * inv0));
        g_y[o0 + 1] = __uint_as_float(f2t(oacc[nt][1] * inv0));
        size_t o1 = ((size_t)(b * Tn + q0 + r0 + 8)) * Cn + h * 64 + d0;
        g_y[o1]     = __uint_as_float(f2t(oacc[nt][2] * inv1));
        g_y[o1 + 1] = __uint_as_float(f2t(oacc[nt][3] * inv1));
    }
}

// ---------------------------------------------------------------------------
extern "C" void kernel_launch(void* const* d_in, const int* in_sizes, int n_in,
                              void* d_out, int out_size)
{
    const float* x      = (const float*)d_in[0];
    const float* b_attn = (const float*)d_in[2];
    const float* b_proj = (const float*)d_in[4];
    const float* w_attn = (const float*)d_in[1];
    const float* w_proj = (const float*)d_in[3];
    float* out = (float*)d_out;

    cudaFuncSetAttribute(attn_tc,
                         cudaFuncAttributeMaxDynamicSharedMemorySize,
                         ATTN_SMEM_BYTES);

    // 0) Pre-convert inputs to tf32
    cvt_tf32<0><<<(Mn * Cn / 4 + 255) / 256, 256>>>(x,      Mn * Cn / 4);
    cvt_tf32<1><<<(Cn * NQKV / 4 + 255) / 256, 256>>>(w_attn, Cn * NQKV / 4);
    cvt_tf32<2><<<(Cn * Cn / 4 + 255) / 256, 256>>>(w_proj, Cn * Cn / 4);

    // 1) QKV = x @ w_attn + b_attn -> tf32 q/k/v ([B,H,T,D])
    gemm_tc<0><<<dim3(NQKV / 128, Mn / 128), 256>>>(b_attn, nullptr);

    // 2) Flash attention -> tf32 g_y
    attn_tc<<<dim3(Tn / 64, Bn * Hn), 128, ATTN_SMEM_BYTES>>>();

    // 3) out = y @ w_proj + b_proj (fp32 out)
    gemm_tc<1><<<dim3(Cn / 128, Mn / 128), 256>>>(b_proj, out);
}